// round 13
// baseline (speedup 1.0000x reference)
#include <cuda_runtime.h>
#include <cuda_bf16.h>
#include <math.h>
#include <stdint.h>

#define CH   512
#define SP   3136
#define NB   32
#define MTOT 100352
#define EPSV 1e-5f

typedef unsigned long long ull;

// ===================== PTX helpers =========================================
__device__ __forceinline__ ull ffma2(ull a, ull b, ull c) {
    ull d;
    asm("fma.rn.f32x2 %0, %1, %2, %3;" : "=l"(d) : "l"(a), "l"(b), "l"(c));
    return d;
}
__device__ __forceinline__ float2 u2f2(ull v) {
    float2 r;
    asm("mov.b64 {%0, %1}, %2;" : "=f"(r.x), "=f"(r.y) : "l"(v));
    return r;
}
__device__ __forceinline__ uint32_t smem_u32(const void* p) {
    uint32_t a;
    asm("{ .reg .u64 t; cvta.to.shared.u64 t, %1; cvt.u32.u64 %0, t; }"
        : "=r"(a) : "l"(p));
    return a;
}
__device__ __forceinline__ void ldsm4(uint32_t r[4], uint32_t a) {
    asm volatile("ldmatrix.sync.aligned.m8n8.x4.shared.b16 {%0,%1,%2,%3}, [%4];"
                 : "=r"(r[0]), "=r"(r[1]), "=r"(r[2]), "=r"(r[3]) : "r"(a));
}
__device__ __forceinline__ void ldsm4t(uint32_t r[4], uint32_t a) {
    asm volatile("ldmatrix.sync.aligned.m8n8.x4.trans.shared.b16 {%0,%1,%2,%3}, [%4];"
                 : "=r"(r[0]), "=r"(r[1]), "=r"(r[2]), "=r"(r[3]) : "r"(a));
}
__device__ __forceinline__ void mma16816(float c[4], const uint32_t a[4],
                                         const uint32_t b[2]) {
    asm volatile("mma.sync.aligned.m16n8k16.row.col.f32.bf16.bf16.f32 "
                 "{%0,%1,%2,%3}, {%4,%5,%6,%7}, {%8,%9}, {%0,%1,%2,%3};"
                 : "+f"(c[0]), "+f"(c[1]), "+f"(c[2]), "+f"(c[3])
                 : "r"(a[0]), "r"(a[1]), "r"(a[2]), "r"(a[3]),
                   "r"(b[0]), "r"(b[1]));
}
__device__ __forceinline__ void cpa16(uint32_t smem, const void* gmem) {
    asm volatile("cp.async.cg.shared.global [%0], [%1], 16;"
                 :: "r"(smem), "l"(gmem));
}
__device__ __forceinline__ void cpa16z(uint32_t smem, const void* gmem, int nb) {
    asm volatile("cp.async.cg.shared.global [%0], [%1], 16, %2;"
                 :: "r"(smem), "l"(gmem), "r"(nb));
}
#define CPA_COMMIT() asm volatile("cp.async.commit_group;" ::: "memory")
#define CPA_WAIT1()  asm volatile("cp.async.wait_group 1;" ::: "memory")
#define CPA_WAIT0()  asm volatile("cp.async.wait_group 0;" ::: "memory")

// ===================== scratch globals =====================================
__device__ __align__(16) __nv_bfloat16 g_Xhi[(size_t)NB * CH * SP];
__device__ __align__(16) __nv_bfloat16 g_Xlo[(size_t)NB * CH * SP];
__device__ __align__(16) __nv_bfloat16 g_Mhi[CH * CH];
__device__ __align__(16) __nv_bfloat16 g_Mlo[CH * CH];
__device__ float g_meanpart[NB * CH];
__device__ float g_mean[CH];
__device__ __align__(16) float g_Gsl[(size_t)NB * CH * CH];
__device__ float g_Sigma[CH * CH];
__device__ float g_SigmaN[CH * CH];
__device__ float g_Pa[CH * CH];
__device__ float g_P2[CH * CH];
__device__ float g_PS[CH * CH];
__device__ float g_M[CH * CH];
__device__ float g_bias[CH];
__device__ float g_scal[2];
__device__ unsigned g_barcnt;
__device__ volatile unsigned g_bargen;

// ===================== convert + fused mean partials =======================
__global__ void __launch_bounds__(256) k_convert(const float* __restrict__ X) {
    const int c = blockIdx.x, b = blockIdx.y;
    const size_t base = ((size_t)b * CH + c) * SP;
    const float* src = X + base;
    float s = 0.f;
    for (int i = threadIdx.x * 4; i < SP; i += 1024) {
        float4 v = *(const float4*)(src + i);
        s += (v.x + v.y) + (v.z + v.w);
        __nv_bfloat16 h0 = __float2bfloat16(v.x), h1 = __float2bfloat16(v.y);
        __nv_bfloat16 h2 = __float2bfloat16(v.z), h3 = __float2bfloat16(v.w);
        __nv_bfloat162 hh0; hh0.x = h0; hh0.y = h1;
        __nv_bfloat162 hh1; hh1.x = h2; hh1.y = h3;
        __nv_bfloat162 ll0, ll1;
        ll0.x = __float2bfloat16(v.x - __bfloat162float(h0));
        ll0.y = __float2bfloat16(v.y - __bfloat162float(h1));
        ll1.x = __float2bfloat16(v.z - __bfloat162float(h2));
        ll1.y = __float2bfloat16(v.w - __bfloat162float(h3));
        *(__nv_bfloat162*)(g_Xhi + base + i)     = hh0;
        *(__nv_bfloat162*)(g_Xhi + base + i + 2) = hh1;
        *(__nv_bfloat162*)(g_Xlo + base + i)     = ll0;
        *(__nv_bfloat162*)(g_Xlo + base + i + 2) = ll1;
    }
    __shared__ float red[256];
    red[threadIdx.x] = s;
    __syncthreads();
    for (int o = 128; o > 0; o >>= 1) {
        if (threadIdx.x < o) red[threadIdx.x] += red[threadIdx.x + o];
        __syncthreads();
    }
    if (threadIdx.x == 0) g_meanpart[b * CH + c] = red[0];
}

__global__ void k_mean_final() {
    const int c = blockIdx.x * 256 + threadIdx.x;
    float s = 0.f;
    #pragma unroll
    for (int b = 0; b < NB; b++) s += g_meanpart[b * CH + c];
    g_mean[c] = s * (1.0f / MTOT);
}

// ===================== Gram via mma.sync + cp.async (2-term split) =========
// G ~= Xhi @ (Xhi + Xlo)^T : A-lo never needed.
// stage: Ahi[128x80B]=10240 | Bhi=10240 | Blo=10240 = 30720; x2 stages
#define G_STG  30720
#define G_SMEM (2 * G_STG)

__global__ void __launch_bounds__(256, 2) k_gram_mma() {
    extern __shared__ char smem[];
    const int tid = threadIdx.x, wid = tid >> 5, lane = tid & 31;
    const int pair = blockIdx.x, slice = blockIdx.y;
    const int PI[10] = {0,0,0,0,1,1,1,2,2,3};
    const int PJ[10] = {0,1,2,3,1,2,3,2,3,3};
    const int m0 = PI[pair] * 128, n0 = PJ[pair] * 128;
    const int wm = (wid & 3) * 32, wn = (wid >> 2) * 64;
    const uint32_t sbase = smem_u32(smem);
    const size_t Bbase = (size_t)slice * CH * SP;

    const int aRow = wm + ((lane >> 3) & 1) * 8 + (lane & 7);
    const int aCol = (lane >> 4) * 16;
    const int bRow = wn + (lane >> 4) * 8 + (lane & 7);
    const int bCol = ((lane >> 3) & 1) * 16;

    float acc[2][8][4];
    #pragma unroll
    for (int mt = 0; mt < 2; mt++)
        #pragma unroll
        for (int nt = 0; nt < 8; nt++)
            #pragma unroll
            for (int q = 0; q < 4; q++) acc[mt][nt][q] = 0.f;

    // 1536 16B segments per stage: mat0=Ahi(m0), mat1=Bhi(n0), mat2=Blo(n0)
#define G_LD(kk, sg) do {                                                    \
    const uint32_t sb0 = sbase + (sg) * G_STG;                               \
    const int kb = (kk) * 32;                                                \
    _Pragma("unroll")                                                        \
    for (int e = 0; e < 6; e++) {                                            \
        const int chunk = e * 256 + tid;                                     \
        const int mat = chunk >> 9;                                          \
        const int idx = chunk & 511;                                         \
        const int row = idx >> 2, q = idx & 3;                               \
        const __nv_bfloat16* bp0 = (mat == 2) ? g_Xlo : g_Xhi;               \
        const int r0 = (mat == 0) ? m0 : n0;                                 \
        cpa16(sb0 + mat * 10240 + row * 80 + q * 16,                         \
              bp0 + Bbase + (size_t)(r0 + row) * SP + kb + q * 8);           \
    }                                                                        \
    CPA_COMMIT();                                                            \
} while (0)

    G_LD(0, 0);
    for (int kk = 0; kk < 98; kk++) {
        if (kk < 97) { G_LD(kk + 1, (kk + 1) & 1); CPA_WAIT1(); }
        else CPA_WAIT0();
        __syncthreads();
        const uint32_t sa = sbase + (kk & 1) * G_STG;
        #pragma unroll
        for (int k16 = 0; k16 < 2; k16++) {
            const int kb = k16 * 32;
            uint32_t ah[2][4], bh[4][4], bl[4][4];
            #pragma unroll
            for (int mt = 0; mt < 2; mt++)
                ldsm4(ah[mt], sa + (aRow + mt * 16) * 80 + kb + aCol);
            #pragma unroll
            for (int np = 0; np < 4; np++) {
                const uint32_t bo = sa + 10240 + (bRow + np * 16) * 80 + kb + bCol;
                ldsm4(bh[np], bo);
                ldsm4(bl[np], bo + 10240);
            }
            #pragma unroll
            for (int mt = 0; mt < 2; mt++)
                #pragma unroll
                for (int np = 0; np < 4; np++) {
                    mma16816(acc[mt][np*2],   ah[mt], &bh[np][0]);
                    mma16816(acc[mt][np*2+1], ah[mt], &bh[np][2]);
                    mma16816(acc[mt][np*2],   ah[mt], &bl[np][0]);
                    mma16816(acc[mt][np*2+1], ah[mt], &bl[np][2]);
                }
        }
        __syncthreads();
    }
#undef G_LD

    float* dst = g_Gsl + (size_t)slice * CH * CH;
    const int g4 = lane >> 2, t2 = (lane & 3) * 2;
    #pragma unroll
    for (int mt = 0; mt < 2; mt++)
        #pragma unroll
        for (int nt = 0; nt < 8; nt++) {
            const int row = m0 + wm + mt * 16 + g4;
            const int col = n0 + wn + nt * 8 + t2;
            float2 v0; v0.x = acc[mt][nt][0]; v0.y = acc[mt][nt][1];
            float2 v1; v1.x = acc[mt][nt][2]; v1.y = acc[mt][nt][3];
            *(float2*)(dst + (size_t)row * CH + col)       = v0;
            *(float2*)(dst + (size_t)(row + 8) * CH + col) = v1;
        }
}

// ===================== Sigma / trace =======================================
__global__ void k_sigma() {
    const int idx = blockIdx.x * 256 + threadIdx.x;
    const int i = idx >> 9, j = idx & 511;
    const size_t off = ((i >> 7) <= (j >> 7)) ? ((size_t)i * CH + j)
                                              : ((size_t)j * CH + i);
    float s = 0.f;
    #pragma unroll 8
    for (int p = 0; p < NB; p++) s += g_Gsl[(size_t)p * CH * CH + off];
    float v = s * (1.0f / MTOT) - g_mean[i] * g_mean[j];
    if (i == j) v += EPSV;
    g_Sigma[idx] = v;
}

__global__ void k_trace() {
    __shared__ float red[512];
    const int t = threadIdx.x;
    red[t] = g_Sigma[t * (CH + 1)];
    __syncthreads();
    for (int o = 256; o > 0; o >>= 1) {
        if (t < o) red[t] += red[t + o];
        __syncthreads();
    }
    if (t == 0) {
        float inv = 1.0f / red[0];
        g_scal[0] = inv;
        g_scal[1] = sqrtf(inv);
    }
}

// ===================== persistent NS + rotP + bias =========================
__device__ __forceinline__ void mm512_acc(const float* __restrict__ A,
                                          const float* __restrict__ B,
                                          int i0, int j0, ull acc[4][2]) {
    __shared__ float As[16][128];
    __shared__ float Bs[16][64];
    const int tid = threadIdx.x;
    const int tx = tid & 15, ty = tid >> 4;
    #pragma unroll
    for (int r = 0; r < 4; r++) { acc[r][0] = 0ull; acc[r][1] = 0ull; }
    const int lr = tid >> 2, lq = (tid & 3) * 4;
    const int kb = tid >> 4, jb = (tid & 15) * 4;
    for (int k0 = 0; k0 < 512; k0 += 16) {
        float4 av = *(const float4*)(A + (size_t)(i0 + lr) * 512 + k0 + lq);
        float4 bv = *(const float4*)(B + (size_t)(k0 + kb) * 512 + j0 + jb);
        __syncthreads();
        As[lq + 0][2 * lr] = av.x; As[lq + 0][2 * lr + 1] = av.x;
        As[lq + 1][2 * lr] = av.y; As[lq + 1][2 * lr + 1] = av.y;
        As[lq + 2][2 * lr] = av.z; As[lq + 2][2 * lr + 1] = av.z;
        As[lq + 3][2 * lr] = av.w; As[lq + 3][2 * lr + 1] = av.w;
        *(float4*)&Bs[kb][jb] = bv;
        __syncthreads();
        #pragma unroll
        for (int kk = 0; kk < 16; kk++) {
            const ull* ap = (const ull*)&As[kk][ty * 8];
            const ull* bp = (const ull*)&Bs[kk][tx * 4];
            ull a[4], bb[2];
            #pragma unroll
            for (int r = 0; r < 4; r++) a[r] = ap[r];
            bb[0] = bp[0]; bb[1] = bp[1];
            #pragma unroll
            for (int r = 0; r < 4; r++) {
                acc[r][0] = ffma2(a[r], bb[0], acc[r][0]);
                acc[r][1] = ffma2(a[r], bb[1], acc[r][1]);
            }
        }
    }
}

// grid-wide barrier: all 128 CTAs resident (grid < #SMs). Snapshot-relative,
// graph-replay safe (g_barcnt returns to 0; g_bargen monotone).
__device__ __forceinline__ void gsync() {
    __threadfence();
    __syncthreads();
    if (threadIdx.x == 0) {
        const unsigned gen = g_bargen;
        if (atomicAdd(&g_barcnt, 1u) == 127u) {
            g_barcnt = 0u;
            __threadfence();
            atomicAdd((unsigned*)&g_bargen, 1u);
        } else {
            while (g_bargen == gen) __nanosleep(64);
        }
    }
    __syncthreads();
}

__global__ void __launch_bounds__(256) k_ns_persist(const float* __restrict__ rot) {
    const int cta = blockIdx.x;            // 0..127
    const int grp = cta >> 6, tile = cta & 63;
    const int i0 = (tile >> 3) * 64, j0 = (tile & 7) * 64;
    const int tid = threadIdx.x;
    const int tx = tid & 15, ty = tid >> 4;

    // prep: SigmaN = Sigma/tr ; P = I  (2048 elems per CTA)
    {
        const float s0 = g_scal[0];
        const int base = cta * 2048;
        for (int t = tid; t < 2048; t += 256) {
            const int idx = base + t;
            g_SigmaN[idx] = g_Sigma[idx] * s0;
            const int i = idx >> 9, j = idx & 511;
            g_Pa[idx] = (i == j) ? 1.0f : 0.0f;
        }
    }
    gsync();

    for (int it = 0; it < 10; it++) {
        // phase A: grp0: P2 = P@P ; grp1: PS = P@SigmaN
        {
            ull acc[4][2];
            const float* Bm = grp ? g_SigmaN : g_Pa;
            float* Cm = grp ? g_PS : g_P2;
            mm512_acc(g_Pa, Bm, i0, j0, acc);
            #pragma unroll
            for (int r = 0; r < 4; r++) {
                float* row = Cm + (size_t)(i0 + ty * 4 + r) * 512 + j0 + tx * 4;
                float2 v0 = u2f2(acc[r][0]), v1 = u2f2(acc[r][1]);
                row[0] = v0.x; row[1] = v0.y; row[2] = v1.x; row[3] = v1.y;
            }
        }
        gsync();
        // phase B: grp0: P = 1.5 P - 0.5 (P2 @ PS) in-place
        if (grp == 0) {
            ull acc[4][2];
            mm512_acc(g_P2, g_PS, i0, j0, acc);
            #pragma unroll
            for (int r = 0; r < 4; r++) {
                const size_t b0 = (size_t)(i0 + ty * 4 + r) * 512 + j0 + tx * 4;
                float2 v0 = u2f2(acc[r][0]), v1 = u2f2(acc[r][1]);
                g_Pa[b0 + 0] = 1.5f * g_Pa[b0 + 0] - 0.5f * v0.x;
                g_Pa[b0 + 1] = 1.5f * g_Pa[b0 + 1] - 0.5f * v0.y;
                g_Pa[b0 + 2] = 1.5f * g_Pa[b0 + 2] - 0.5f * v1.x;
                g_Pa[b0 + 3] = 1.5f * g_Pa[b0 + 3] - 0.5f * v1.y;
            }
        }
        gsync();
    }

    // rotP: M = rot @ P * sqrt(1/tr) + split (grp0 only)
    if (grp == 0) {
        ull acc[4][2];
        mm512_acc(rot, g_Pa, i0, j0, acc);
        const float s = g_scal[1];
        #pragma unroll
        for (int r = 0; r < 4; r++) {
            const size_t b0 = (size_t)(i0 + ty * 4 + r) * 512 + j0 + tx * 4;
            float2 v0 = u2f2(acc[r][0]), v1 = u2f2(acc[r][1]);
            float vv[4] = {v0.x * s, v0.y * s, v1.x * s, v1.y * s};
            #pragma unroll
            for (int q = 0; q < 4; q++) {
                g_M[b0 + q] = vv[q];
                __nv_bfloat16 h = __float2bfloat16(vv[q]);
                g_Mhi[b0 + q] = h;
                g_Mlo[b0 + q] = __float2bfloat16(vv[q] - __bfloat162float(h));
            }
        }
    }
    gsync();

    // bias: rows cta*4 .. cta*4+3 ; 64 threads per row
    {
        __shared__ float rb[8];
        const int rgrp = tid >> 6, l64 = tid & 63;
        const int row = cta * 4 + rgrp;
        float s = 0.f;
        for (int c = l64; c < CH; c += 64) s += g_M[(size_t)row * CH + c] * g_mean[c];
        #pragma unroll
        for (int o = 16; o > 0; o >>= 1) s += __shfl_down_sync(0xffffffffu, s, o);
        if ((tid & 31) == 0) rb[tid >> 5] = s;
        __syncthreads();
        if (tid < 4) g_bias[cta * 4 + tid] = rb[tid * 2] + rb[tid * 2 + 1];
    }
}

// ===================== out = M@X - bias via mma.sync + cp.async ============
#define O_STG  36864
#define O_SMEM (2 * O_STG)

__global__ void __launch_bounds__(256, 2) k_out_mma(float* __restrict__ out) {
    extern __shared__ char smem[];
    const int tid = threadIdx.x, wid = tid >> 5, lane = tid & 31;
    const int b = blockIdx.z;
    const int i0 = blockIdx.y * 128;
    const int s0 = blockIdx.x * 128;
    const int wm = (wid & 3) * 32, wn = (wid >> 2) * 64;
    const uint32_t sbase = smem_u32(smem);
    const size_t Xb = (size_t)b * CH * SP;

    const int aRow = wm + ((lane >> 3) & 1) * 8 + (lane & 7);
    const int aCol = (lane >> 4) * 16;
    const int bKr  = ((lane >> 3) & 1) * 8 + (lane & 7);
    const int bGg  = (wn >> 3) + (lane >> 4);

    float acc[2][8][4];
    #pragma unroll
    for (int mt = 0; mt < 2; mt++)
        #pragma unroll
        for (int nt = 0; nt < 8; nt++)
            #pragma unroll
            for (int q = 0; q < 4; q++) acc[mt][nt][q] = 0.f;

#define O_LD(kk, sg) do {                                                    \
    const uint32_t sb0 = sbase + (sg) * O_STG;                               \
    const int k0 = (kk) * 32;                                                \
    _Pragma("unroll")                                                        \
    for (int e = 0; e < 8; e++) {                                            \
        const int chunk = e * 256 + tid;                                     \
        const int mat = chunk >> 9;                                          \
        const int idx = chunk & 511;                                         \
        if (mat < 2) {                                                       \
            const int row = idx >> 2, q = idx & 3;                           \
            const __nv_bfloat16* src = (mat ? g_Mlo : g_Mhi)                 \
                + (size_t)(i0 + row) * CH + k0 + q * 8;                      \
            cpa16(sb0 + mat * 10240 + row * 80 + q * 16, src);               \
        } else {                                                             \
            const int kr = idx >> 4, sg2 = idx & 15;                         \
            const int sc = s0 + sg2 * 8;                                     \
            const int nb = (sc + 8 <= SP) ? 16 : 0;                          \
            const __nv_bfloat16* src = ((mat & 1) ? g_Xlo : g_Xhi) + Xb      \
                + (size_t)(k0 + kr) * SP + ((sc + 8 <= SP) ? sc : 0);        \
            cpa16z(sb0 + 20480 + (mat & 1) * 8192 + kr * 256                 \
                   + (((sg2) ^ (kr & 7)) << 4), src, nb);                    \
        }                                                                    \
    }                                                                        \
    CPA_COMMIT();                                                            \
} while (0)

    O_LD(0, 0);
    for (int kk = 0; kk < 16; kk++) {
        if (kk < 15) { O_LD(kk + 1, (kk + 1) & 1); CPA_WAIT1(); }
        else CPA_WAIT0();
        __syncthreads();
        const uint32_t sa = sbase + (kk & 1) * O_STG;
        #pragma unroll
        for (int k16 = 0; k16 < 2; k16++) {
            uint32_t ah[2][4], al[2][4], bh[4][4], bl[4][4];
            #pragma unroll
            for (int mt = 0; mt < 2; mt++) {
                const uint32_t ao = sa + (aRow + mt * 16) * 80 + k16 * 32 + aCol;
                ldsm4(ah[mt], ao);
                ldsm4(al[mt], ao + 10240);
            }
            const int kr = k16 * 16 + bKr;
            #pragma unroll
            for (int np = 0; np < 4; np++) {
                const uint32_t bo = sa + 20480 + kr * 256 +
                                    (((bGg + np * 2) ^ (kr & 7)) << 4);
                ldsm4t(bh[np], bo);
                ldsm4t(bl[np], bo + 8192);
            }
            #pragma unroll
            for (int mt = 0; mt < 2; mt++)
                #pragma unroll
                for (int np = 0; np < 4; np++) {
                    mma16816(acc[mt][np*2],   ah[mt], &bh[np][0]);
                    mma16816(acc[mt][np*2+1], ah[mt], &bh[np][2]);
                    mma16816(acc[mt][np*2],   ah[mt], &bl[np][0]);
                    mma16816(acc[mt][np*2+1], ah[mt], &bl[np][2]);
                    mma16816(acc[mt][np*2],   al[mt], &bh[np][0]);
                    mma16816(acc[mt][np*2+1], al[mt], &bh[np][2]);
                }
        }
        __syncthreads();
    }
#undef O_LD

    const int g4 = lane >> 2, t2 = (lane & 3) * 2;
    float* Ob = out + Xb;
    #pragma unroll
    for (int mt = 0; mt < 2; mt++) {
        const int gi = i0 + wm + mt * 16 + g4;
        const float b0 = g_bias[gi], b1 = g_bias[gi + 8];
        #pragma unroll
        for (int nt = 0; nt < 8; nt++) {
            const int col = s0 + wn + nt * 8 + t2;
            if (col < SP) {
                float2 v0; v0.x = acc[mt][nt][0] - b0; v0.y = acc[mt][nt][1] - b0;
                float2 v1; v1.x = acc[mt][nt][2] - b1; v1.y = acc[mt][nt][3] - b1;
                *(float2*)(Ob + (size_t)gi * SP + col)       = v0;
                *(float2*)(Ob + (size_t)(gi + 8) * SP + col) = v1;
            }
        }
    }
}

// ===================== launch ==============================================
extern "C" void kernel_launch(void* const* d_in, const int* in_sizes, int n_in,
                              void* d_out, int out_size) {
    const float* X   = (const float*)d_in[0];
    const float* rot = (const float*)d_in[1];
    float* out = (float*)d_out;
    (void)in_sizes; (void)n_in; (void)out_size;

    cudaFuncSetAttribute(k_gram_mma, cudaFuncAttributeMaxDynamicSharedMemorySize, G_SMEM);
    cudaFuncSetAttribute(k_out_mma,  cudaFuncAttributeMaxDynamicSharedMemorySize, O_SMEM);

    k_convert<<<dim3(CH, NB), 256>>>(X);          // 1
    k_mean_final<<<2, 256>>>();                   // 2
    k_mean_final<<<2, 256>>>();                   // 3 (slot pad; idempotent)
    k_gram_mma<<<dim3(10, NB), 256, G_SMEM>>>();  // 4 <- ncu slot
    k_sigma<<<1024, 256>>>();
    k_trace<<<1, 512>>>();
    k_ns_persist<<<128, 256>>>(rot);
    k_out_mma<<<dim3(25, 4, NB), 256, O_SMEM>>>(out);
}